// round 16
// baseline (speedup 1.0000x reference)
#include <cuda_runtime.h>
#include <math.h>
#include <cstdint>

// ---------------------------------------------------------------------------
// STN fp32 on FFMA2 (rt=3 banking ceiling = the wall; tensor paths closed on
// this toolchain). R16: harvest launch-overhead slack —
//  - head fused into conv3 (last-block atomic ticket, replay-safe modulo)
//  - weights staged in smem (all 4 constant-memcpy graph nodes dropped)
//  - sampler theta via uniform __ldg (no smem/sync)
// ---------------------------------------------------------------------------

__device__ __align__(16) float g_P1[16u * 127 * 127 * 16];
__device__ __align__(16) float g_P2[16u * 62 * 62 * 32];
__device__ __align__(16) float g_part[16][16][32];
__device__ __align__(16) float g_theta[16 * 6];
__device__ int g_cnt[16];   // zero-init; monotone across replays, used mod 16

// ---- packed f32x2 helpers (FFMA2: PTX-only, ptxas never emits) ------------
__device__ __forceinline__ unsigned long long pack2(float v) {
    unsigned long long r;
    asm("mov.b64 %0, {%1, %1};" : "=l"(r) : "r"(__float_as_uint(v)));
    return r;
}
__device__ __forceinline__ void ffma2(unsigned long long& a, unsigned long long v,
                                      unsigned long long w) {
    asm("fma.rn.f32x2 %0, %1, %2, %0;" : "+l"(a) : "l"(v), "l"(w));
}
__device__ __forceinline__ float2 unpack2(unsigned long long a) {
    float lo, hi;
    asm("mov.b64 {%0, %1}, %2;" : "=f"(lo), "=f"(hi) : "l"(a));
    return make_float2(lo, hi);
}

// ---------------------------------------------------------------------------
// conv1: x(16,256,256,32)*W1+b1 -> relu -> pool2 -> P1(16,127,127,16)
// 256 thr = 128 slots x 2 cout-groups. Weights staged once in smem.
// ---------------------------------------------------------------------------
__global__ __launch_bounds__(256, 2) void conv1_kernel(
    const float* __restrict__ x, const float* __restrict__ W,
    const float* __restrict__ bias)
{
    __shared__ __align__(16) float sIn[4][34][36];
    __shared__ __align__(16) float sW[3 * 3 * 32 * 16];
    __shared__ float sB[16];

    const int b  = blockIdx.z;
    const int by = blockIdx.y, bx = blockIdx.x;
    const int t  = threadIdx.x;
    const int grp  = t >> 7;
    const int slot = t & 127;
    const int py   = slot >> 3;
    const int pxi  = slot & 7;
    const int r0 = by * 32, c0 = bx * 32;

    for (int i = t; i < 4608; i += 256) sW[i] = W[i];
    if (t < 16) sB[t] = bias[t];

    unsigned long long acc[2][4][4];
#pragma unroll
    for (int dr = 0; dr < 2; ++dr)
#pragma unroll
        for (int dc = 0; dc < 4; ++dc)
#pragma unroll
            for (int j = 0; j < 4; ++j) acc[dr][dc][j] = 0ULL;

    for (int cc = 0; cc < 8; ++cc) {
        __syncthreads();
        for (int i = t; i < 34 * 34; i += 256) {
            int r = i / 34, c = i - 34 * (i / 34);
            int gr = r0 + r, gc = c0 + c;
            float4 v = make_float4(0.f, 0.f, 0.f, 0.f);
            if (gr < 256 && gc < 256)
                v = *(const float4*)(x + (((size_t)(b * 256 + gr) * 256 + gc) * 32 + cc * 4));
            sIn[0][r][c] = v.x; sIn[1][r][c] = v.y;
            sIn[2][r][c] = v.z; sIn[3][r][c] = v.w;
        }
        __syncthreads();

#pragma unroll
        for (int ci = 0; ci < 4; ++ci) {
            float v[4][6];
#pragma unroll
            for (int dr = 0; dr < 4; ++dr) {
                const float* row = &sIn[ci][2 * py + dr][4 * pxi];
                float4 f = *(const float4*)row;
                float2 g = *(const float2*)(row + 4);
                v[dr][0] = f.x; v[dr][1] = f.y; v[dr][2] = f.z;
                v[dr][3] = f.w; v[dr][4] = g.x; v[dr][5] = g.y;
            }
#pragma unroll
            for (int ky = 0; ky < 3; ++ky)
#pragma unroll
                for (int kx = 0; kx < 3; ++kx) {
                    const ulonglong2* wp = (const ulonglong2*)
                        &sW[(((ky * 3 + kx) * 32) + cc * 4 + ci) * 16 + 8 * grp];
                    ulonglong2 qa = wp[0], qb = wp[1];
#pragma unroll
                    for (int dr = 0; dr < 2; ++dr)
#pragma unroll
                        for (int dc = 0; dc < 4; ++dc) {
                            unsigned long long vv = pack2(v[ky + dr][kx + dc]);
                            ffma2(acc[dr][dc][0], vv, qa.x);
                            ffma2(acc[dr][dc][1], vv, qa.y);
                            ffma2(acc[dr][dc][2], vv, qb.x);
                            ffma2(acc[dr][dc][3], vv, qb.y);
                        }
                }
        }
    }

    const int ph = by * 16 + py;
#pragma unroll
    for (int s = 0; s < 2; ++s) {
        const int pw = bx * 16 + 2 * pxi + s;
        if (ph < 127 && pw < 127) {
            float* op = g_P1 + ((size_t)(b * 127 + ph) * 127 + pw) * 16 + 8 * grp;
#pragma unroll
            for (int j = 0; j < 4; ++j) {
                float2 a0 = unpack2(acc[0][2 * s][j]);
                float2 a1 = unpack2(acc[0][2 * s + 1][j]);
                float2 a2 = unpack2(acc[1][2 * s][j]);
                float2 a3 = unpack2(acc[1][2 * s + 1][j]);
                float mlo = fmaxf(fmaxf(a0.x, a1.x), fmaxf(a2.x, a3.x));
                float mhi = fmaxf(fmaxf(a0.y, a1.y), fmaxf(a2.y, a3.y));
                op[2 * j]     = fmaxf(mlo + sB[8 * grp + 2 * j], 0.f);
                op[2 * j + 1] = fmaxf(mhi + sB[8 * grp + 2 * j + 1], 0.f);
            }
        }
    }
}

// ---------------------------------------------------------------------------
// conv2: P1*W2+b2 -> relu -> pool -> P2. Weights staged once in smem.
// ---------------------------------------------------------------------------
__global__ __launch_bounds__(256, 2) void conv2_kernel(
    const float* __restrict__ W, const float* __restrict__ bias)
{
    __shared__ __align__(16) float sIn[4][18][36];
    __shared__ __align__(16) float sW[3 * 3 * 16 * 32];
    __shared__ float sB[32];

    const int b  = blockIdx.z;
    const int by = blockIdx.y, bx = blockIdx.x;
    const int t  = threadIdx.x;
    const int grp  = t >> 6;
    const int slot = t & 63;
    const int py   = slot >> 3;
    const int pxi  = slot & 7;
    const int r0 = by * 16, c0 = bx * 32;

    for (int i = t; i < 4608; i += 256) sW[i] = W[i];
    if (t < 32) sB[t] = bias[t];

    unsigned long long acc[2][4][4];
#pragma unroll
    for (int dr = 0; dr < 2; ++dr)
#pragma unroll
        for (int dc = 0; dc < 4; ++dc)
#pragma unroll
            for (int j = 0; j < 4; ++j) acc[dr][dc][j] = 0ULL;

    for (int cc = 0; cc < 4; ++cc) {
        __syncthreads();
        for (int i = t; i < 18 * 34; i += 256) {
            int r = i / 34, c = i - 34 * (i / 34);
            int gr = r0 + r, gc = c0 + c;
            float4 v = make_float4(0.f, 0.f, 0.f, 0.f);
            if (gr < 127 && gc < 127)
                v = *(const float4*)(g_P1 + (((size_t)(b * 127 + gr) * 127 + gc) * 16 + cc * 4));
            sIn[0][r][c] = v.x; sIn[1][r][c] = v.y;
            sIn[2][r][c] = v.z; sIn[3][r][c] = v.w;
        }
        __syncthreads();

#pragma unroll
        for (int ci = 0; ci < 4; ++ci) {
            float v[4][6];
#pragma unroll
            for (int dr = 0; dr < 4; ++dr) {
                const float* row = &sIn[ci][2 * py + dr][4 * pxi];
                float4 f = *(const float4*)row;
                float2 g = *(const float2*)(row + 4);
                v[dr][0] = f.x; v[dr][1] = f.y; v[dr][2] = f.z;
                v[dr][3] = f.w; v[dr][4] = g.x; v[dr][5] = g.y;
            }
#pragma unroll
            for (int ky = 0; ky < 3; ++ky)
#pragma unroll
                for (int kx = 0; kx < 3; ++kx) {
                    const ulonglong2* wp = (const ulonglong2*)
                        &sW[(((ky * 3 + kx) * 16) + cc * 4 + ci) * 32 + 8 * grp];
                    ulonglong2 qa = wp[0], qb = wp[1];
#pragma unroll
                    for (int dr = 0; dr < 2; ++dr)
#pragma unroll
                        for (int dc = 0; dc < 4; ++dc) {
                            unsigned long long vv = pack2(v[ky + dr][kx + dc]);
                            ffma2(acc[dr][dc][0], vv, qa.x);
                            ffma2(acc[dr][dc][1], vv, qa.y);
                            ffma2(acc[dr][dc][2], vv, qb.x);
                            ffma2(acc[dr][dc][3], vv, qb.y);
                        }
                }
        }
    }

    const int ph = by * 8 + py;
#pragma unroll
    for (int s = 0; s < 2; ++s) {
        const int pw = bx * 16 + 2 * pxi + s;
        if (ph < 62 && pw < 62) {
            float* op = g_P2 + ((size_t)(b * 62 + ph) * 62 + pw) * 32 + 8 * grp;
#pragma unroll
            for (int j = 0; j < 4; ++j) {
                float2 a0 = unpack2(acc[0][2 * s][j]);
                float2 a1 = unpack2(acc[0][2 * s + 1][j]);
                float2 a2 = unpack2(acc[1][2 * s][j]);
                float2 a3 = unpack2(acc[1][2 * s + 1][j]);
                float mlo = fmaxf(fmaxf(a0.x, a1.x), fmaxf(a2.x, a3.x));
                float mhi = fmaxf(fmaxf(a0.y, a1.y), fmaxf(a2.y, a3.y));
                op[2 * j]     = fmaxf(mlo + sB[8 * grp + 2 * j], 0.f);
                op[2 * j + 1] = fmaxf(mhi + sB[8 * grp + 2 * j + 1], 0.f);
            }
        }
    }
}

// ---------------------------------------------------------------------------
// conv3 + fused head: P2*W3+b3 -> relu -> pool -> tile channel sums; the
// last CTA per batch (atomic ticket) computes mean -> dense chain -> theta.
// ---------------------------------------------------------------------------
__global__ __launch_bounds__(128, 4) void conv3_kernel(
    const float* __restrict__ W, const float* __restrict__ bias,
    const float* __restrict__ D1, const float* __restrict__ db1,
    const float* __restrict__ D2, const float* __restrict__ db2,
    const float* __restrict__ D3, const float* __restrict__ db3)
{
    __shared__ __align__(16) float sIn[4][18][20];
    __shared__ __align__(16) float sW[9 * 4 * 32];
    __shared__ float sRed[32][32];
    __shared__ int sTicket;
    __shared__ float h0[32], h1[64], h2[32];

    const int b = blockIdx.z, by = blockIdx.y, bx = blockIdx.x;
    const int t = threadIdx.x;
    const int grp = t >> 5, slot = t & 31, py = slot >> 2, pxi = slot & 3;
    const int r0 = by * 16, c0 = bx * 16;

    unsigned long long acc[2][4][4];
#pragma unroll
    for (int dr = 0; dr < 2; ++dr)
#pragma unroll
        for (int dc = 0; dc < 4; ++dc)
#pragma unroll
            for (int j = 0; j < 4; ++j) acc[dr][dc][j] = 0ULL;

    for (int cc = 0; cc < 8; ++cc) {
        __syncthreads();
        for (int i = t; i < 18 * 18; i += 128) {
            int rr = i / 18, c = i - 18 * (i / 18);
            int gr = r0 + rr, gc = c0 + c;
            float4 v = make_float4(0.f, 0.f, 0.f, 0.f);
            if (gr < 62 && gc < 62)
                v = *(const float4*)(g_P2 + (((size_t)(b * 62 + gr) * 62 + gc) * 32 + cc * 4));
            sIn[0][rr][c] = v.x; sIn[1][rr][c] = v.y;
            sIn[2][rr][c] = v.z; sIn[3][rr][c] = v.w;
        }
        for (int i = t; i < 1152; i += 128) {
            int kk = i >> 7, rem = i & 127;
            int ci = rem >> 5, co = rem & 31;
            sW[i] = W[((kk * 32) + cc * 4 + ci) * 32 + co];
        }
        __syncthreads();
#pragma unroll
        for (int ci = 0; ci < 4; ++ci) {
            float v[4][6];
#pragma unroll
            for (int dr = 0; dr < 4; ++dr) {
                const float* row = &sIn[ci][2 * py + dr][4 * pxi];
                float4 f = *(const float4*)row;
                float2 g = *(const float2*)(row + 4);
                v[dr][0] = f.x; v[dr][1] = f.y; v[dr][2] = f.z;
                v[dr][3] = f.w; v[dr][4] = g.x; v[dr][5] = g.y;
            }
#pragma unroll
            for (int ky = 0; ky < 3; ++ky)
#pragma unroll
                for (int kx = 0; kx < 3; ++kx) {
                    const ulonglong2* wp = (const ulonglong2*)
                        &sW[((ky * 3 + kx) * 4 + ci) * 32 + 8 * grp];
                    ulonglong2 qa = wp[0], qb = wp[1];
#pragma unroll
                    for (int dr = 0; dr < 2; ++dr)
#pragma unroll
                        for (int dc = 0; dc < 4; ++dc) {
                            unsigned long long vv = pack2(v[ky + dr][kx + dc]);
                            ffma2(acc[dr][dc][0], vv, qa.x);
                            ffma2(acc[dr][dc][1], vv, qa.y);
                            ffma2(acc[dr][dc][2], vv, qb.x);
                            ffma2(acc[dr][dc][3], vv, qb.y);
                        }
                }
        }
    }

    const int ph = by * 8 + py;
    float csum[8];
#pragma unroll
    for (int j = 0; j < 8; ++j) csum[j] = 0.f;
#pragma unroll
    for (int s = 0; s < 2; ++s) {
        const int pw = bx * 8 + 2 * pxi + s;
        const bool valid = (ph < 30) && (pw < 30);
#pragma unroll
        for (int j = 0; j < 4; ++j) {
            float2 a0 = unpack2(acc[0][2 * s][j]);
            float2 a1 = unpack2(acc[0][2 * s + 1][j]);
            float2 a2 = unpack2(acc[1][2 * s][j]);
            float2 a3 = unpack2(acc[1][2 * s + 1][j]);
            float mlo = fmaxf(fmaxf(a0.x, a1.x), fmaxf(a2.x, a3.x));
            float mhi = fmaxf(fmaxf(a0.y, a1.y), fmaxf(a2.y, a3.y));
            float vlo = fmaxf(mlo + bias[8 * grp + 2 * j], 0.f);
            float vhi = fmaxf(mhi + bias[8 * grp + 2 * j + 1], 0.f);
            if (valid) { csum[2 * j] += vlo; csum[2 * j + 1] += vhi; }
        }
    }
    __syncthreads();
#pragma unroll
    for (int j = 0; j < 8; ++j) sRed[slot][8 * grp + j] = csum[j];
    __syncthreads();

    if (t < 32) {
        float s = 0.f;
#pragma unroll
        for (int p = 0; p < 32; ++p) s += sRed[p][t];
        g_part[b][by * 4 + bx][t] = s;
    }

    // ---- last-CTA-per-batch head (atomic ticket; replay-safe modulo) ----
    __threadfence();
    __syncthreads();
    if (t == 0) sTicket = atomicAdd(&g_cnt[b], 1) & 15;
    __syncthreads();
    if (sTicket != 15) return;

    __threadfence();   // acquire side: make all 16 CTAs' g_part visible
    if (t < 32) {
        float s = 0.f;
#pragma unroll
        for (int tile = 0; tile < 16; ++tile) s += g_part[b][tile][t];
        h0[t] = s * (1.f / 900.f);
    }
    __syncthreads();
    if (t < 64) {
        float a = db1[t];
#pragma unroll
        for (int k = 0; k < 32; ++k) a = fmaf(h0[k], D1[k * 64 + t], a);
        h1[t] = fmaxf(a, 0.f);
    }
    __syncthreads();
    if (t < 32) {
        float a = db2[t];
#pragma unroll
        for (int k = 0; k < 64; ++k) a = fmaf(h1[k], D2[k * 32 + t], a);
        h2[t] = fmaxf(a, 0.f);
    }
    __syncthreads();
    if (t < 6) {
        float a = db3[t];
#pragma unroll
        for (int k = 0; k < 32; ++k) a = fmaf(h2[k], D3[k * 6 + t], a);
        g_theta[b * 6 + t] = a;
    }
}

// ---------------------------------------------------------------------------
// sampler: affine grid + bilinear sample of x(16,256,256,32).
// ---------------------------------------------------------------------------
__global__ __launch_bounds__(256) void sampler_kernel(
    const float* __restrict__ x, float* __restrict__ out)
{
    const int b = blockIdx.y;
    const float th0 = __ldg(&g_theta[b * 6 + 0]);
    const float th1 = __ldg(&g_theta[b * 6 + 1]);
    const float th2 = __ldg(&g_theta[b * 6 + 2]);
    const float th3 = __ldg(&g_theta[b * 6 + 3]);
    const float th4 = __ldg(&g_theta[b * 6 + 4]);
    const float th5 = __ldg(&g_theta[b * 6 + 5]);

    const int idx = blockIdx.x * 64 + (threadIdx.x >> 2);
    const int c8 = (threadIdx.x & 3) * 8;
    const int i = idx >> 8, j = idx & 255;

    const float xs = -1.f + (float)j * (2.f / 255.f);
    const float ys = -1.f + (float)i * (2.f / 255.f);
    const float xc = th0 * xs + th1 * ys + th2;
    const float yc = th3 * xs + th4 * ys + th5;
    const float xf = 0.5f * ((xc + 1.0f) * 254.0f);
    const float yf = 0.5f * ((yc + 1.0f) * 254.0f);

    int x0 = (int)floorf(xf), x1 = x0 + 1;
    int y0 = (int)floorf(yf), y1 = y0 + 1;
    x0 = min(max(x0, 0), 255); x1 = min(max(x1, 0), 255);
    y0 = min(max(y0, 0), 255); y1 = min(max(y1, 0), 255);

    const float x0f = (float)x0, x1f = (float)x1;
    const float y0f = (float)y0, y1f = (float)y1;
    const float wa = (x1f - xf) * (y1f - yf);
    const float wb = (x1f - xf) * (yf - y0f);
    const float wc = (xf - x0f) * (y1f - yf);
    const float wd = (xf - x0f) * (yf - y0f);

    const float* xb = x + (size_t)b * 256 * 256 * 32;
    const float* pa = xb + ((size_t)(y0 * 256 + x0) * 32 + c8);
    const float* pb = xb + ((size_t)(y1 * 256 + x0) * 32 + c8);
    const float* pc = xb + ((size_t)(y0 * 256 + x1) * 32 + c8);
    const float* pd = xb + ((size_t)(y1 * 256 + x1) * 32 + c8);
    float* po = out + ((size_t)(b * 65536 + idx) * 32 + c8);

#pragma unroll
    for (int h = 0; h < 2; ++h) {
        const float4 Ia = __ldg((const float4*)(pa + 4 * h));
        const float4 Ib = __ldg((const float4*)(pb + 4 * h));
        const float4 Ic = __ldg((const float4*)(pc + 4 * h));
        const float4 Id = __ldg((const float4*)(pd + 4 * h));
        float4 rr;
        rr.x = wa * Ia.x + wb * Ib.x + wc * Ic.x + wd * Id.x;
        rr.y = wa * Ia.y + wb * Ib.y + wc * Ic.y + wd * Id.y;
        rr.z = wa * Ia.z + wb * Ib.z + wc * Ic.z + wd * Id.z;
        rr.w = wa * Ia.w + wb * Ib.w + wc * Ic.w + wd * Id.w;
        *(float4*)(po + 4 * h) = rr;
    }
}

// ---------------------------------------------------------------------------
extern "C" void kernel_launch(void* const* d_in, const int* in_sizes, int n_in,
                              void* d_out, int out_size)
{
    const float* x   = (const float*)d_in[0];
    const float* W1  = (const float*)d_in[1];
    const float* b1  = (const float*)d_in[2];
    const float* W2  = (const float*)d_in[3];
    const float* b2  = (const float*)d_in[4];
    const float* W3  = (const float*)d_in[5];
    const float* b3  = (const float*)d_in[6];
    const float* D1  = (const float*)d_in[7];
    const float* db1 = (const float*)d_in[8];
    const float* D2  = (const float*)d_in[9];
    const float* db2 = (const float*)d_in[10];
    const float* D3  = (const float*)d_in[11];
    const float* db3 = (const float*)d_in[12];
    float* out = (float*)d_out;

    conv1_kernel<<<dim3(8, 8, 16), 256>>>(x, W1, b1);
    conv2_kernel<<<dim3(4, 8, 16), 256>>>(W2, b2);
    conv3_kernel<<<dim3(4, 4, 16), 128>>>(W3, b3, D1, db1, D2, db2, D3, db3);
    sampler_kernel<<<dim3(1024, 16), 256>>>(x, out);
}